// round 5
// baseline (speedup 1.0000x reference)
#include <cuda_runtime.h>
#include <math.h>

#define NPTS   500000
#define MCLUS  50000

typedef unsigned long long u64;

__device__ float g_agg[(size_t)MCLUS * 132];   // 131 used + 1 pad
__device__ float g_h[(size_t)MCLUS * 128];

// ---------------- helpers ----------------
__device__ __forceinline__ u64 pack2(float lo, float hi) {
    u64 r;
    asm("mov.b64 %0, {%1,%2};" : "=l"(r) : "f"(lo), "f"(hi));
    return r;
}
__device__ __forceinline__ u64 fma2(u64 a, u64 b, u64 c) {
    u64 d;
    asm("fma.rn.f32x2 %0, %1, %2, %3;" : "=l"(d) : "l"(a), "l"(b), "l"(c));
    return d;
}
__device__ __forceinline__ float2 unpack2(u64 v) {
    float2 f;
    asm("mov.b64 {%0,%1}, %2;" : "=f"(f.x), "=f"(f.y) : "l"(v));
    return f;
}
__device__ __forceinline__ void red4(float* addr, float a, float b, float c, float d) {
    asm volatile("red.global.add.v4.f32 [%0], {%1,%2,%3,%4};"
                 :: "l"(addr), "f"(a), "f"(b), "f"(c), "f"(d) : "memory");
}
__device__ __forceinline__ float elem4(float4 v, int e) {
    return (e == 0) ? v.x : (e == 1) ? v.y : (e == 2) ? v.z : v.w;
}
__device__ __forceinline__ void cpasync16(void* smem_dst, const void* gsrc) {
    unsigned saddr = (unsigned)__cvta_generic_to_shared(smem_dst);
    asm volatile("cp.async.ca.shared.global [%0], [%1], 16;" :: "r"(saddr), "l"(gsrc));
}
__device__ __forceinline__ void cp_commit() { asm volatile("cp.async.commit_group;"); }
__device__ __forceinline__ void cp_wait0()  { asm volatile("cp.async.wait_group 0;" ::: "memory"); }

#define TSTRIDE 33   // float4 per tile row (conflict-free: 33*16 mod 128 = 16)

// ---------------- kernel 0: zero agg ----------------
__global__ void zero_agg_kernel() {
    const size_t total4 = (size_t)MCLUS * 132 / 4;
    float4* p = (float4*)g_agg;
    float4 z = make_float4(0.f, 0.f, 0.f, 0.f);
    for (size_t i = blockIdx.x * blockDim.x + threadIdx.x; i < total4;
         i += (size_t)gridDim.x * blockDim.x)
        p[i] = z;
}

// ============ kernel 1: attention MLP + weighted scatter ============
// 128 rows/block, 256 thr: cg = tid&3 (16 of 64 cols), rg = tid>>2 (rows rg, rg+64)
__global__ void __launch_bounds__(256, 2) att_scatter_kernel(
    const float* __restrict__ feat, const float* __restrict__ pts,
    const float* __restrict__ ctr, const int* __restrict__ lab,
    const float* __restrict__ aW1, const float* __restrict__ ab1,
    const float* __restrict__ aW2, const float* __restrict__ ab2)
{
    extern __shared__ char dynRaw[];
    ulonglong2* sW  = (ulonglong2*)dynRaw;                        // 131*16
    float4*    sT   = (float4*)(dynRaw + 131 * 16 * 16);          // 128*TSTRIDE
    float*     sB1  = (float*)(dynRaw + 131 * 16 * 16 + 128 * TSTRIDE * 16);
    float*     sA2  = sB1 + 64;
    float*     sRel = sA2 + 64;          // 128*3
    int*       sLab = (int*)(sRel + 384);// 128
    float*     sb2p = (float*)(sLab + 128);

    const int tid = threadIdx.x;
    const int gbase = blockIdx.x * 128;
    const float4* f4 = (const float4*)feat;

    // stage act tile first (overlaps weight staging)
    for (int idx = tid; idx < 128 * 32; idx += 256) {
        int row = idx >> 5, c4 = idx & 31;
        int gr = gbase + row; if (gr >= NPTS) gr = NPTS - 1;
        cpasync16(&sT[row * TSTRIDE + c4], f4 + (size_t)gr * 32 + c4);
    }
    cp_commit();

    // weights swizzled [k][q][cg]
    {
        const ulonglong2* wsrc = (const ulonglong2*)aW1;
        for (int idx = tid; idx < 131 * 16; idx += 256) {
            int k = idx >> 4, c = idx & 15;
            sW[k * 16 + (c & 3) * 4 + (c >> 2)] = wsrc[idx];
        }
        if (tid < 64) { sB1[tid] = ab1[tid]; sA2[tid] = aW2[tid]; }
        if (tid == 0) *sb2p = ab2[0];
        if (tid < 128) {
            int row = gbase + tid;
            int rc = (row < NPTS) ? row : (NPTS - 1);
            int l = lab[rc];
            sLab[tid] = l;
            sRel[tid * 3 + 0] = ctr[l * 3 + 0] - pts[rc * 3 + 0];
            sRel[tid * 3 + 1] = ctr[l * 3 + 1] - pts[rc * 3 + 1];
            sRel[tid * 3 + 2] = ctr[l * 3 + 2] - pts[rc * 3 + 2];
        }
    }
    cp_wait0();
    __syncthreads();

    const int cg = tid & 3;
    const int rg = tid >> 2;

    u64 acc[16];
    {
        const u64* b2 = (const u64*)sB1;
#pragma unroll
        for (int j = 0; j < 8; j++) {
            u64 bb = b2[cg * 8 + j];
            acc[j] = bb; acc[8 + j] = bb;
        }
    }

#pragma unroll 4
    for (int c = 0; c < 32; c++) {
        float4 av0 = sT[rg * TSTRIDE + c];
        float4 av1 = sT[(rg + 64) * TSTRIDE + c];
#pragma unroll
        for (int e = 0; e < 4; e++) {
            const ulonglong2* wp = sW + (c * 4 + e) * 16 + cg;
            ulonglong2 wa = wp[0], wb = wp[4], wc = wp[8], wd = wp[12];
            u64 wv[8] = {wa.x, wa.y, wb.x, wb.y, wc.x, wc.y, wd.x, wd.y};
            float a0 = elem4(av0, e), a1 = elem4(av1, e);
            u64 t0 = pack2(a0, a0), t1 = pack2(a1, a1);
#pragma unroll
            for (int j = 0; j < 8; j++) {
                acc[j]     = fma2(t0, wv[j], acc[j]);
                acc[8 + j] = fma2(t1, wv[j], acc[8 + j]);
            }
        }
    }
    // rel dims k = 128..130
#pragma unroll
    for (int e = 0; e < 3; e++) {
        const ulonglong2* wp = sW + (128 + e) * 16 + cg;
        ulonglong2 wa = wp[0], wb = wp[4], wc = wp[8], wd = wp[12];
        u64 wv[8] = {wa.x, wa.y, wb.x, wb.y, wc.x, wc.y, wd.x, wd.y};
        float r0 = sRel[rg * 3 + e], r1 = sRel[(rg + 64) * 3 + e];
        u64 t0 = pack2(r0, r0), t1 = pack2(r1, r1);
#pragma unroll
        for (int j = 0; j < 8; j++) {
            acc[j]     = fma2(t0, wv[j], acc[j]);
            acc[8 + j] = fma2(t1, wv[j], acc[8 + j]);
        }
    }

    // relu + dot aW2, reduce over 4 cg lanes (all lanes get full sum), sigmoid
    float att0, att1;
    {
        float s0 = 0.f, s1 = 0.f;
#pragma unroll
        for (int j = 0; j < 8; j++) {
            float w0 = sA2[cg * 16 + 2 * j];
            float w1 = sA2[cg * 16 + 2 * j + 1];
            float2 h0 = unpack2(acc[j]);
            float2 h1 = unpack2(acc[8 + j]);
            s0 += fmaxf(h0.x, 0.f) * w0 + fmaxf(h0.y, 0.f) * w1;
            s1 += fmaxf(h1.x, 0.f) * w0 + fmaxf(h1.y, 0.f) * w1;
        }
        s0 += __shfl_xor_sync(0xffffffffu, s0, 1);
        s0 += __shfl_xor_sync(0xffffffffu, s0, 2);
        s1 += __shfl_xor_sync(0xffffffffu, s1, 1);
        s1 += __shfl_xor_sync(0xffffffffu, s1, 2);
        float b2v = *sb2p;
        att0 = 1.f / (1.f + expf(-(s0 + b2v)));
        att1 = 1.f / (1.f + expf(-(s1 + b2v)));
    }

    // scatter from the persistent smem tile (no re-read, no extra barrier)
#pragma unroll 1
    for (int r = 0; r < 2; r++) {
        int rl = rg + r * 64;
        int row = gbase + rl;
        if (row >= NPTS) continue;
        float a = r ? att1 : att0;
        int l = sLab[rl];
        float* arow = g_agg + (size_t)l * 132;
#pragma unroll
        for (int t = 0; t < 8; t++) {
            int ck = cg * 8 + t;
            float4 v = sT[rl * TSTRIDE + ck];
            red4(arow + ck * 4, v.x * a, v.y * a, v.z * a, v.w * a);
        }
        if (cg == 0)
            red4(arow + 128, sRel[rl * 3 + 0] * a, sRel[rl * 3 + 1] * a,
                 sRel[rl * 3 + 2] * a, 0.f);
    }
}

// ============ kernel 2: h = relu(agg @ oW1 + ob1) ============
// grid (391, 2): y = 64-col slice; 128 rows/block
__global__ void __launch_bounds__(256, 2) gemmB_kernel(
    const float* __restrict__ oW1, const float* __restrict__ ob1)
{
    extern __shared__ char dynRaw[];
    ulonglong2* sW = (ulonglong2*)dynRaw;                 // 132*16 (row 131 = 0)
    float4*    sT  = (float4*)(dynRaw + 132 * 16 * 16);   // 128*TSTRIDE

    const int tid = threadIdx.x;
    const int slice = blockIdx.y;
    const int gbase = blockIdx.x * 128;
    const float4* a4 = (const float4*)g_agg;   // 33 f4 per row

    for (int idx = tid; idx < 128 * 33; idx += 256) {
        int row = idx / 33, c4 = idx % 33;
        int gr = gbase + row; if (gr >= MCLUS) gr = MCLUS - 1;
        cpasync16(&sT[row * TSTRIDE + c4], a4 + (size_t)gr * 33 + c4);
    }
    cp_commit();
    {
        const ulonglong2* wsrc = (const ulonglong2*)oW1;   // 131 x 32
        for (int idx = tid; idx < 131 * 16; idx += 256) {
            int k = idx >> 4, c = idx & 15;
            sW[k * 16 + (c & 3) * 4 + (c >> 2)] = wsrc[k * 32 + slice * 16 + c];
        }
        if (tid < 16) {
            ulonglong2 z; z.x = 0ull; z.y = 0ull;
            sW[131 * 16 + tid] = z;
        }
    }
    cp_wait0();
    __syncthreads();

    const int cg = tid & 3;
    const int rg = tid >> 2;

    u64 acc[16];
    {
        const u64* b2 = (const u64*)ob1;
#pragma unroll
        for (int j = 0; j < 8; j++) {
            u64 bb = __ldg(b2 + slice * 32 + cg * 8 + j);
            acc[j] = bb; acc[8 + j] = bb;
        }
    }

#pragma unroll 4
    for (int c = 0; c < 33; c++) {       // 132 k incl zero-padded 131
        float4 av0 = sT[rg * TSTRIDE + c];
        float4 av1 = sT[(rg + 64) * TSTRIDE + c];
#pragma unroll
        for (int e = 0; e < 4; e++) {
            const ulonglong2* wp = sW + (c * 4 + e) * 16 + cg;
            ulonglong2 wa = wp[0], wb = wp[4], wc = wp[8], wd = wp[12];
            u64 wv[8] = {wa.x, wa.y, wb.x, wb.y, wc.x, wc.y, wd.x, wd.y};
            float a0 = elem4(av0, e), a1 = elem4(av1, e);
            u64 t0 = pack2(a0, a0), t1 = pack2(a1, a1);
#pragma unroll
            for (int j = 0; j < 8; j++) {
                acc[j]     = fma2(t0, wv[j], acc[j]);
                acc[8 + j] = fma2(t1, wv[j], acc[8 + j]);
            }
        }
    }

#pragma unroll
    for (int r = 0; r < 2; r++) {
        int rr = gbase + rg + r * 64;
        if (rr < MCLUS) {
            float2* hp = (float2*)(g_h + (size_t)rr * 128 + slice * 64 + cg * 16);
#pragma unroll
            for (int j = 0; j < 8; j++) {
                float2 v = unpack2(acc[r * 8 + j]);
                v.x = fmaxf(v.x, 0.f);
                v.y = fmaxf(v.y, 0.f);
                hp[j] = v;
            }
        }
    }
}

// ============ kernel 3: out = relu(h @ oW2 + ob2) ============
// grid (391, 4): y = 64-col slice; 128 rows/block
__global__ void __launch_bounds__(256, 2) gemmC_kernel(
    const float* __restrict__ oW2, const float* __restrict__ ob2,
    float* __restrict__ out)
{
    extern __shared__ char dynRaw[];
    ulonglong2* sW = (ulonglong2*)dynRaw;                 // 128*16
    float4*    sT  = (float4*)(dynRaw + 128 * 16 * 16);   // 128*TSTRIDE

    const int tid = threadIdx.x;
    const int slice = blockIdx.y;
    const int gbase = blockIdx.x * 128;
    const float4* h4 = (const float4*)g_h;   // 32 f4 per row

    for (int idx = tid; idx < 128 * 32; idx += 256) {
        int row = idx >> 5, c4 = idx & 31;
        int gr = gbase + row; if (gr >= MCLUS) gr = MCLUS - 1;
        cpasync16(&sT[row * TSTRIDE + c4], h4 + (size_t)gr * 32 + c4);
    }
    cp_commit();
    {
        const ulonglong2* wsrc = (const ulonglong2*)oW2;   // 128 x 64
        for (int idx = tid; idx < 128 * 16; idx += 256) {
            int k = idx >> 4, c = idx & 15;
            sW[k * 16 + (c & 3) * 4 + (c >> 2)] = wsrc[k * 64 + slice * 16 + c];
        }
    }
    cp_wait0();
    __syncthreads();

    const int cg = tid & 3;
    const int rg = tid >> 2;

    u64 acc[16];
    {
        const u64* b2 = (const u64*)ob2;
#pragma unroll
        for (int j = 0; j < 8; j++) {
            u64 bb = __ldg(b2 + slice * 32 + cg * 8 + j);
            acc[j] = bb; acc[8 + j] = bb;
        }
    }

#pragma unroll 4
    for (int c = 0; c < 32; c++) {
        float4 av0 = sT[rg * TSTRIDE + c];
        float4 av1 = sT[(rg + 64) * TSTRIDE + c];
#pragma unroll
        for (int e = 0; e < 4; e++) {
            const ulonglong2* wp = sW + (c * 4 + e) * 16 + cg;
            ulonglong2 wa = wp[0], wb = wp[4], wc = wp[8], wd = wp[12];
            u64 wv[8] = {wa.x, wa.y, wb.x, wb.y, wc.x, wc.y, wd.x, wd.y};
            float a0 = elem4(av0, e), a1 = elem4(av1, e);
            u64 t0 = pack2(a0, a0), t1 = pack2(a1, a1);
#pragma unroll
            for (int j = 0; j < 8; j++) {
                acc[j]     = fma2(t0, wv[j], acc[j]);
                acc[8 + j] = fma2(t1, wv[j], acc[8 + j]);
            }
        }
    }

#pragma unroll
    for (int r = 0; r < 2; r++) {
        int rr = gbase + rg + r * 64;
        if (rr < MCLUS) {
            float2* op = (float2*)(out + (size_t)rr * 256 + slice * 64 + cg * 16);
#pragma unroll
            for (int j = 0; j < 8; j++) {
                float2 v = unpack2(acc[r * 8 + j]);
                v.x = fmaxf(v.x, 0.f);
                v.y = fmaxf(v.y, 0.f);
                op[j] = v;
            }
        }
    }
}

extern "C" void kernel_launch(void* const* d_in, const int* in_sizes, int n_in,
                              void* d_out, int out_size) {
    const float* feat = (const float*)d_in[0];
    const float* pts  = (const float*)d_in[1];
    const float* ctr  = (const float*)d_in[2];
    const int*   lab  = (const int*)d_in[3];
    const float* aW1  = (const float*)d_in[4];
    const float* ab1  = (const float*)d_in[5];
    const float* aW2  = (const float*)d_in[6];
    const float* ab2  = (const float*)d_in[7];
    const float* oW1  = (const float*)d_in[8];
    const float* ob1  = (const float*)d_in[9];
    const float* oW2  = (const float*)d_in[10];
    const float* ob2  = (const float*)d_in[11];
    float* out = (float*)d_out;

    const int attSmem = 131 * 16 * 16 + 128 * TSTRIDE * 16 + (64 + 64 + 384) * 4 + 128 * 4 + 16;
    const int bSmem   = 132 * 16 * 16 + 128 * TSTRIDE * 16;
    const int cSmem   = 128 * 16 * 16 + 128 * TSTRIDE * 16;

    static int inited = 0;
    if (!inited) {
        cudaFuncSetAttribute(att_scatter_kernel, cudaFuncAttributeMaxDynamicSharedMemorySize, attSmem);
        cudaFuncSetAttribute(gemmB_kernel, cudaFuncAttributeMaxDynamicSharedMemorySize, bSmem);
        cudaFuncSetAttribute(gemmC_kernel, cudaFuncAttributeMaxDynamicSharedMemorySize, cSmem);
        inited = 1;
    }

    zero_agg_kernel<<<2048, 256>>>();
    att_scatter_kernel<<<(NPTS + 127) / 128, 256, attSmem>>>(feat, pts, ctr, lab,
                                                             aW1, ab1, aW2, ab2);
    gemmB_kernel<<<dim3((MCLUS + 127) / 128, 2), 256, bSmem>>>(oW1, ob1);
    gemmC_kernel<<<dim3((MCLUS + 127) / 128, 4), 256, cSmem>>>(oW2, ob2, out);
}

// round 6
// speedup vs baseline: 1.3423x; 1.3423x over previous
#include <cuda_runtime.h>
#include <math.h>

#define NPTS   500000
#define MCLUS  50000

typedef unsigned long long u64;

__device__ float g_agg[(size_t)MCLUS * 132];   // 131 used + 1 pad
__device__ float g_h[(size_t)MCLUS * 128];

// ---------------- helpers ----------------
__device__ __forceinline__ u64 pack2(float lo, float hi) {
    u64 r;
    asm("mov.b64 %0, {%1,%2};" : "=l"(r) : "f"(lo), "f"(hi));
    return r;
}
__device__ __forceinline__ u64 fma2(u64 a, u64 b, u64 c) {
    u64 d;
    asm("fma.rn.f32x2 %0, %1, %2, %3;" : "=l"(d) : "l"(a), "l"(b), "l"(c));
    return d;
}
__device__ __forceinline__ float2 unpack2(u64 v) {
    float2 f;
    asm("mov.b64 {%0,%1}, %2;" : "=f"(f.x), "=f"(f.y) : "l"(v));
    return f;
}
__device__ __forceinline__ void red4(float* addr, float a, float b, float c, float d) {
    asm volatile("red.global.add.v4.f32 [%0], {%1,%2,%3,%4};"
                 :: "l"(addr), "f"(a), "f"(b), "f"(c), "f"(d) : "memory");
}
__device__ __forceinline__ float elem4(float4 v, int e) {
    return (e == 0) ? v.x : (e == 1) ? v.y : (e == 2) ? v.z : v.w;
}
__device__ __forceinline__ void cpasync16(void* smem_dst, const void* gsrc) {
    unsigned saddr = (unsigned)__cvta_generic_to_shared(smem_dst);
    asm volatile("cp.async.ca.shared.global [%0], [%1], 16;" :: "r"(saddr), "l"(gsrc));
}
__device__ __forceinline__ void cp_commit() { asm volatile("cp.async.commit_group;"); }
__device__ __forceinline__ void cp_wait0()  { asm volatile("cp.async.wait_group 0;" ::: "memory"); }

#define ACT_STRIDE 5           // float4 per row in act buffer (conflict-free)
#define ACT_BUF    (256 * ACT_STRIDE)   // float4 per buffer

// ---------------- kernel 0: zero agg ----------------
__global__ void zero_agg_kernel() {
    const size_t total4 = (size_t)MCLUS * 132 / 4;
    float4* p = (float4*)g_agg;
    float4 z = make_float4(0.f, 0.f, 0.f, 0.f);
    for (size_t i = blockIdx.x * blockDim.x + threadIdx.x; i < total4;
         i += (size_t)gridDim.x * blockDim.x)
        p[i] = z;
}

// ============ kernel 1: attention MLP + weighted scatter ============
// 256 thr: cg = tid&3 (16 of 64 cols), rg = tid>>2; thread rows = rg + r*64.
__global__ void __launch_bounds__(256, 2) att_scatter_kernel(
    const float* __restrict__ feat, const float* __restrict__ pts,
    const float* __restrict__ ctr, const int* __restrict__ lab,
    const float* __restrict__ aW1, const float* __restrict__ ab1,
    const float* __restrict__ aW2, const float* __restrict__ ab2)
{
    extern __shared__ char dynRaw[];
    ulonglong2* sW  = (ulonglong2*)dynRaw;                       // 131*16
    float4*    sAct = (float4*)(dynRaw + 131 * 16 * 16);         // 2 * ACT_BUF
    float*     sB1  = (float*)(dynRaw + 131 * 16 * 16 + 2 * ACT_BUF * 16);
    float*     sA2  = sB1 + 64;
    float*     sRel = sA2 + 64;          // 256*3
    float*     sAtt = sRel + 768;        // 256
    int*       sLab = (int*)(sAtt + 256);
    float*     sb2p = (float*)(sLab + 256);

    const int tid = threadIdx.x;
    const int wid = tid >> 5;
    const int gbase = blockIdx.x * 256;
    const float4* f4 = (const float4*)feat;

    // stage weights swizzled [k][q][cg]
    {
        const ulonglong2* wsrc = (const ulonglong2*)aW1;
        for (int idx = tid; idx < 131 * 16; idx += 256) {
            int k = idx >> 4, c = idx & 15;
            sW[k * 16 + (c & 3) * 4 + (c >> 2)] = wsrc[idx];
        }
        if (tid < 64) { sB1[tid] = ab1[tid]; sA2[tid] = aW2[tid]; }
        if (tid == 0) *sb2p = ab2[0];
        int row = gbase + tid;
        int rc = (row < NPTS) ? row : (NPTS - 1);
        int l = lab[rc];
        sLab[tid] = l;
        sRel[tid * 3 + 0] = ctr[l * 3 + 0] - pts[rc * 3 + 0];
        sRel[tid * 3 + 1] = ctr[l * 3 + 1] - pts[rc * 3 + 1];
        sRel[tid * 3 + 2] = ctr[l * 3 + 2] - pts[rc * 3 + 2];
    }

    // issue chunk 0
    {
        for (int idx = tid; idx < 256 * 4; idx += 256) {
            int row = idx >> 2, c4 = idx & 3;
            int gr = gbase + row; if (gr >= NPTS) gr = NPTS - 1;
            cpasync16(&sAct[row * ACT_STRIDE + c4], f4 + (size_t)gr * 32 + c4);
        }
        cp_commit();
    }
    __syncthreads();   // weights/rel ready

    const int cg = tid & 3;
    const int rg = tid >> 2;

    u64 acc[32];
    {
        const u64* b2 = (const u64*)sB1;
#pragma unroll
        for (int j = 0; j < 8; j++) {
            u64 bb = b2[cg * 8 + j];
#pragma unroll
            for (int r = 0; r < 4; r++) acc[r * 8 + j] = bb;
        }
    }

#pragma unroll 1
    for (int c = 0; c < 8; c++) {
        cp_wait0();
        __syncthreads();
        if (c < 7) {
            float4* dst = sAct + ((c + 1) & 1) * ACT_BUF;
            for (int idx = tid; idx < 256 * 4; idx += 256) {
                int row = idx >> 2, c4 = idx & 3;
                int gr = gbase + row; if (gr >= NPTS) gr = NPTS - 1;
                cpasync16(&dst[row * ACT_STRIDE + c4], f4 + (size_t)gr * 32 + (c + 1) * 4 + c4);
            }
            cp_commit();
        }
        const float4* A = sAct + (c & 1) * ACT_BUF;
#pragma unroll
        for (int kk = 0; kk < 4; kk++) {
            int k4 = (kk + wid) & 3;   // warp-staggered order: de-correlate stalls
            float4 av[4];
#pragma unroll
            for (int r = 0; r < 4; r++) av[r] = A[(rg + r * 64) * ACT_STRIDE + k4];
#pragma unroll
            for (int e = 0; e < 4; e++) {
                const ulonglong2* wp = sW + (c * 16 + k4 * 4 + e) * 16 + cg;
                ulonglong2 wa = wp[0], wb = wp[4], wc = wp[8], wd = wp[12];
                u64 wv[8] = {wa.x, wa.y, wb.x, wb.y, wc.x, wc.y, wd.x, wd.y};
#pragma unroll
                for (int r = 0; r < 4; r++) {
                    float ae = elem4(av[r], e);
                    u64 tp = pack2(ae, ae);
#pragma unroll
                    for (int j = 0; j < 8; j++)
                        acc[r * 8 + j] = fma2(tp, wv[j], acc[r * 8 + j]);
                }
            }
        }
    }

    // rel-coord dims k = 128..130
#pragma unroll
    for (int e = 0; e < 3; e++) {
        const ulonglong2* wp = sW + (128 + e) * 16 + cg;
        ulonglong2 wa = wp[0], wb = wp[4], wc = wp[8], wd = wp[12];
        u64 wv[8] = {wa.x, wa.y, wb.x, wb.y, wc.x, wc.y, wd.x, wd.y};
#pragma unroll
        for (int r = 0; r < 4; r++) {
            float rv = sRel[(rg + r * 64) * 3 + e];
            u64 tp = pack2(rv, rv);
#pragma unroll
            for (int j = 0; j < 8; j++)
                acc[r * 8 + j] = fma2(tp, wv[j], acc[r * 8 + j]);
        }
    }

    // relu + dot aW2, reduce over cg lanes, sigmoid -> sAtt
    {
        float s[4] = {0.f, 0.f, 0.f, 0.f};
#pragma unroll
        for (int j = 0; j < 8; j++) {
            float w0 = sA2[cg * 16 + 2 * j];
            float w1 = sA2[cg * 16 + 2 * j + 1];
#pragma unroll
            for (int r = 0; r < 4; r++) {
                float2 h = unpack2(acc[r * 8 + j]);
                s[r] += fmaxf(h.x, 0.f) * w0 + fmaxf(h.y, 0.f) * w1;
            }
        }
        float b2v = *sb2p;
#pragma unroll
        for (int r = 0; r < 4; r++) {
            s[r] += __shfl_xor_sync(0xffffffffu, s[r], 1);
            s[r] += __shfl_xor_sync(0xffffffffu, s[r], 2);
            if (cg == 0)
                sAtt[rg + r * 64] = 1.f / (1.f + expf(-(s[r] + b2v)));
        }
    }
    __syncthreads();

    // scatter phase: restage feat chunks coalesced, red4 from smem
    {
        for (int idx = tid; idx < 256 * 4; idx += 256) {
            int row = idx >> 2, c4 = idx & 3;
            int gr = gbase + row; if (gr >= NPTS) gr = NPTS - 1;
            cpasync16(&sAct[row * ACT_STRIDE + c4], f4 + (size_t)gr * 32 + c4);
        }
        cp_commit();
    }
#pragma unroll 1
    for (int c = 0; c < 8; c++) {
        cp_wait0();
        __syncthreads();
        if (c < 7) {
            float4* dst = sAct + ((c + 1) & 1) * ACT_BUF;
            for (int idx = tid; idx < 256 * 4; idx += 256) {
                int row = idx >> 2, c4 = idx & 3;
                int gr = gbase + row; if (gr >= NPTS) gr = NPTS - 1;
                cpasync16(&dst[row * ACT_STRIDE + c4], f4 + (size_t)gr * 32 + (c + 1) * 4 + c4);
            }
            cp_commit();
        }
        const float4* A = sAct + (c & 1) * ACT_BUF;
#pragma unroll
        for (int r = 0; r < 4; r++) {
            int rl = rg + r * 64;
            int row = gbase + rl;
            if (row < NPTS) {
                float a = sAtt[rl];
                int l = sLab[rl];
                float4 v = A[rl * ACT_STRIDE + cg];
                red4(g_agg + (size_t)l * 132 + (c * 4 + cg) * 4,
                     v.x * a, v.y * a, v.z * a, v.w * a);
            }
        }
    }
    if (cg == 0) {
#pragma unroll
        for (int r = 0; r < 4; r++) {
            int rl = rg + r * 64;
            int row = gbase + rl;
            if (row < NPTS) {
                float a = sAtt[rl];
                int l = sLab[rl];
                red4(g_agg + (size_t)l * 132 + 128,
                     sRel[rl * 3 + 0] * a, sRel[rl * 3 + 1] * a,
                     sRel[rl * 3 + 2] * a, 0.f);
            }
        }
    }
}

// ============ kernel 2: h = relu(agg @ oW1 + ob1) ============
// grid (196, 2): y = 64-col slice.
__global__ void __launch_bounds__(256, 2) gemmB_kernel(
    const float* __restrict__ oW1, const float* __restrict__ ob1)
{
    extern __shared__ char dynRaw[];
    ulonglong2* sW  = (ulonglong2*)dynRaw;                 // 131*16
    float4*    sAct = (float4*)(dynRaw + 131 * 16 * 16);   // 2 * ACT_BUF

    const int tid = threadIdx.x;
    const int wid = tid >> 5;
    const int slice = blockIdx.y;
    const int gbase = blockIdx.x * 256;
    const float4* a4 = (const float4*)g_agg;   // 33 f4 per row

    {
        const ulonglong2* wsrc = (const ulonglong2*)oW1;   // 131 x 32
        for (int idx = tid; idx < 131 * 16; idx += 256) {
            int k = idx >> 4, c = idx & 15;
            sW[k * 16 + (c & 3) * 4 + (c >> 2)] = wsrc[k * 32 + slice * 16 + c];
        }
    }
    {
        for (int idx = tid; idx < 256 * 4; idx += 256) {
            int row = idx >> 2, c4 = idx & 3;
            int gr = gbase + row; if (gr >= MCLUS) gr = MCLUS - 1;
            cpasync16(&sAct[row * ACT_STRIDE + c4], a4 + (size_t)gr * 33 + c4);
        }
        cp_commit();
    }
    __syncthreads();

    const int cg = tid & 3;
    const int rg = tid >> 2;

    u64 acc[32];
    {
        const u64* b2 = (const u64*)ob1;
#pragma unroll
        for (int j = 0; j < 8; j++) {
            u64 bb = __ldg(b2 + slice * 32 + cg * 8 + j);
#pragma unroll
            for (int r = 0; r < 4; r++) acc[r * 8 + j] = bb;
        }
    }

#pragma unroll 1
    for (int c = 0; c < 8; c++) {
        cp_wait0();
        __syncthreads();
        if (c < 7) {
            float4* dst = sAct + ((c + 1) & 1) * ACT_BUF;
            for (int idx = tid; idx < 256 * 4; idx += 256) {
                int row = idx >> 2, c4 = idx & 3;
                int gr = gbase + row; if (gr >= MCLUS) gr = MCLUS - 1;
                cpasync16(&dst[row * ACT_STRIDE + c4], a4 + (size_t)gr * 33 + (c + 1) * 4 + c4);
            }
            cp_commit();
        }
        const float4* A = sAct + (c & 1) * ACT_BUF;
#pragma unroll
        for (int kk = 0; kk < 4; kk++) {
            int k4 = (kk + wid) & 3;   // warp-staggered
            float4 av[4];
#pragma unroll
            for (int r = 0; r < 4; r++) av[r] = A[(rg + r * 64) * ACT_STRIDE + k4];
#pragma unroll
            for (int e = 0; e < 4; e++) {
                const ulonglong2* wp = sW + (c * 16 + k4 * 4 + e) * 16 + cg;
                ulonglong2 wa = wp[0], wb = wp[4], wc = wp[8], wd = wp[12];
                u64 wv[8] = {wa.x, wa.y, wb.x, wb.y, wc.x, wc.y, wd.x, wd.y};
#pragma unroll
                for (int r = 0; r < 4; r++) {
                    float ae = elem4(av[r], e);
                    u64 tp = pack2(ae, ae);
#pragma unroll
                    for (int j = 0; j < 8; j++)
                        acc[r * 8 + j] = fma2(tp, wv[j], acc[r * 8 + j]);
                }
            }
        }
    }

    // tail k = 128..130 (k=131 is zero pad in agg; skip)
    {
        float4 tv[4];
#pragma unroll
        for (int r = 0; r < 4; r++) {
            int gr = gbase + rg + r * 64; if (gr >= MCLUS) gr = MCLUS - 1;
            tv[r] = a4[(size_t)gr * 33 + 32];
        }
#pragma unroll
        for (int e = 0; e < 3; e++) {
            const ulonglong2* wp = sW + (128 + e) * 16 + cg;
            ulonglong2 wa = wp[0], wb = wp[4], wc = wp[8], wd = wp[12];
            u64 wv[8] = {wa.x, wa.y, wb.x, wb.y, wc.x, wc.y, wd.x, wd.y};
#pragma unroll
            for (int r = 0; r < 4; r++) {
                float ae = elem4(tv[r], e);
                u64 tp = pack2(ae, ae);
#pragma unroll
                for (int j = 0; j < 8; j++)
                    acc[r * 8 + j] = fma2(tp, wv[j], acc[r * 8 + j]);
            }
        }
    }

#pragma unroll
    for (int r = 0; r < 4; r++) {
        int rr = gbase + rg + r * 64;
        if (rr < MCLUS) {
            float2* hp = (float2*)(g_h + (size_t)rr * 128 + slice * 64 + cg * 16);
#pragma unroll
            for (int j = 0; j < 8; j++) {
                float2 v = unpack2(acc[r * 8 + j]);
                v.x = fmaxf(v.x, 0.f);
                v.y = fmaxf(v.y, 0.f);
                hp[j] = v;
            }
        }
    }
}

// ============ kernel 3: out = relu(h @ oW2 + ob2) ============
// grid (196, 4): y = 64-col slice.
__global__ void __launch_bounds__(256, 2) gemmC_kernel(
    const float* __restrict__ oW2, const float* __restrict__ ob2,
    float* __restrict__ out)
{
    extern __shared__ char dynRaw[];
    ulonglong2* sW  = (ulonglong2*)dynRaw;                 // 128*16
    float4*    sAct = (float4*)(dynRaw + 128 * 16 * 16);   // 2 * ACT_BUF

    const int tid = threadIdx.x;
    const int wid = tid >> 5;
    const int slice = blockIdx.y;
    const int gbase = blockIdx.x * 256;
    const float4* h4 = (const float4*)g_h;   // 32 f4 per row

    {
        const ulonglong2* wsrc = (const ulonglong2*)oW2;   // 128 x 64
        for (int idx = tid; idx < 128 * 16; idx += 256) {
            int k = idx >> 4, c = idx & 15;
            sW[k * 16 + (c & 3) * 4 + (c >> 2)] = wsrc[k * 64 + slice * 16 + c];
        }
    }
    {
        for (int idx = tid; idx < 256 * 4; idx += 256) {
            int row = idx >> 2, c4 = idx & 3;
            int gr = gbase + row; if (gr >= MCLUS) gr = MCLUS - 1;
            cpasync16(&sAct[row * ACT_STRIDE + c4], h4 + (size_t)gr * 32 + c4);
        }
        cp_commit();
    }
    __syncthreads();

    const int cg = tid & 3;
    const int rg = tid >> 2;

    u64 acc[32];
    {
        const u64* b2 = (const u64*)ob2;
#pragma unroll
        for (int j = 0; j < 8; j++) {
            u64 bb = __ldg(b2 + slice * 32 + cg * 8 + j);
#pragma unroll
            for (int r = 0; r < 4; r++) acc[r * 8 + j] = bb;
        }
    }

#pragma unroll 1
    for (int c = 0; c < 8; c++) {
        cp_wait0();
        __syncthreads();
        if (c < 7) {
            float4* dst = sAct + ((c + 1) & 1) * ACT_BUF;
            for (int idx = tid; idx < 256 * 4; idx += 256) {
                int row = idx >> 2, c4 = idx & 3;
                int gr = gbase + row; if (gr >= MCLUS) gr = MCLUS - 1;
                cpasync16(&dst[row * ACT_STRIDE + c4], h4 + (size_t)gr * 32 + (c + 1) * 4 + c4);
            }
            cp_commit();
        }
        const float4* A = sAct + (c & 1) * ACT_BUF;
#pragma unroll
        for (int kk = 0; kk < 4; kk++) {
            int k4 = (kk + wid) & 3;   // warp-staggered
            float4 av[4];
#pragma unroll
            for (int r = 0; r < 4; r++) av[r] = A[(rg + r * 64) * ACT_STRIDE + k4];
#pragma unroll
            for (int e = 0; e < 4; e++) {
                const ulonglong2* wp = sW + (c * 16 + k4 * 4 + e) * 16 + cg;
                ulonglong2 wa = wp[0], wb = wp[4], wc = wp[8], wd = wp[12];
                u64 wv[8] = {wa.x, wa.y, wb.x, wb.y, wc.x, wc.y, wd.x, wd.y};
#pragma unroll
                for (int r = 0; r < 4; r++) {
                    float ae = elem4(av[r], e);
                    u64 tp = pack2(ae, ae);
#pragma unroll
                    for (int j = 0; j < 8; j++)
                        acc[r * 8 + j] = fma2(tp, wv[j], acc[r * 8 + j]);
                }
            }
        }
    }

#pragma unroll
    for (int r = 0; r < 4; r++) {
        int rr = gbase + rg + r * 64;
        if (rr < MCLUS) {
            float2* op = (float2*)(out + (size_t)rr * 256 + slice * 64 + cg * 16);
#pragma unroll
            for (int j = 0; j < 8; j++) {
                float2 v = unpack2(acc[r * 8 + j]);
                v.x = fmaxf(v.x, 0.f);
                v.y = fmaxf(v.y, 0.f);
                op[j] = v;
            }
        }
    }
}

extern "C" void kernel_launch(void* const* d_in, const int* in_sizes, int n_in,
                              void* d_out, int out_size) {
    const float* feat = (const float*)d_in[0];
    const float* pts  = (const float*)d_in[1];
    const float* ctr  = (const float*)d_in[2];
    const int*   lab  = (const int*)d_in[3];
    const float* aW1  = (const float*)d_in[4];
    const float* ab1  = (const float*)d_in[5];
    const float* aW2  = (const float*)d_in[6];
    const float* ab2  = (const float*)d_in[7];
    const float* oW1  = (const float*)d_in[8];
    const float* ob1  = (const float*)d_in[9];
    const float* oW2  = (const float*)d_in[10];
    const float* ob2  = (const float*)d_in[11];
    float* out = (float*)d_out;

    const int attSmem  = 131 * 16 * 16 + 2 * ACT_BUF * 16 + (64 + 64 + 768 + 256 + 1) * 4 + 256 * 4;
    const int bSmem    = 131 * 16 * 16 + 2 * ACT_BUF * 16;
    const int cSmem    = 128 * 16 * 16 + 2 * ACT_BUF * 16;

    static int inited = 0;
    if (!inited) {
        cudaFuncSetAttribute(att_scatter_kernel, cudaFuncAttributeMaxDynamicSharedMemorySize, attSmem);
        cudaFuncSetAttribute(gemmB_kernel, cudaFuncAttributeMaxDynamicSharedMemorySize, bSmem);
        cudaFuncSetAttribute(gemmC_kernel, cudaFuncAttributeMaxDynamicSharedMemorySize, cSmem);
        inited = 1;
    }

    zero_agg_kernel<<<2048, 256>>>();
    att_scatter_kernel<<<(NPTS + 255) / 256, 256, attSmem>>>(feat, pts, ctr, lab,
                                                             aW1, ab1, aW2, ab2);
    gemmB_kernel<<<dim3((MCLUS + 255) / 256, 2), 256, bSmem>>>(oW1, ob1);
    gemmC_kernel<<<dim3((MCLUS + 255) / 256, 4), 256, cSmem>>>(oW2, ob2, out);
}

// round 7
// speedup vs baseline: 1.5656x; 1.1663x over previous
#include <cuda_runtime.h>
#include <math.h>

#define NPTS   500000
#define MCLUS  50000

typedef unsigned long long u64;

__device__ float g_agg[(size_t)MCLUS * 132];   // 131 used + 1 pad
__device__ float g_h[(size_t)MCLUS * 128];

// ---------------- helpers ----------------
__device__ __forceinline__ u64 pack2(float lo, float hi) {
    u64 r;
    asm("mov.b64 %0, {%1,%2};" : "=l"(r) : "f"(lo), "f"(hi));
    return r;
}
__device__ __forceinline__ u64 fma2(u64 a, u64 b, u64 c) {
    u64 d;
    asm("fma.rn.f32x2 %0, %1, %2, %3;" : "=l"(d) : "l"(a), "l"(b), "l"(c));
    return d;
}
__device__ __forceinline__ float2 unpack2(u64 v) {
    float2 f;
    asm("mov.b64 {%0,%1}, %2;" : "=f"(f.x), "=f"(f.y) : "l"(v));
    return f;
}
__device__ __forceinline__ void red4(float* addr, float a, float b, float c, float d) {
    asm volatile("red.global.add.v4.f32 [%0], {%1,%2,%3,%4};"
                 :: "l"(addr), "f"(a), "f"(b), "f"(c), "f"(d) : "memory");
}
__device__ __forceinline__ float elem4(float4 v, int e) {
    return (e == 0) ? v.x : (e == 1) ? v.y : (e == 2) ? v.z : v.w;
}
__device__ __forceinline__ void cpasync16(void* smem_dst, const void* gsrc) {
    unsigned saddr = (unsigned)__cvta_generic_to_shared(smem_dst);
    asm volatile("cp.async.ca.shared.global [%0], [%1], 16;" :: "r"(saddr), "l"(gsrc));
}
__device__ __forceinline__ void cp_commit() { asm volatile("cp.async.commit_group;"); }
__device__ __forceinline__ void cp_wait0()  { asm volatile("cp.async.wait_group 0;" ::: "memory"); }

__device__ __forceinline__ unsigned cvt_tf32(float f) {
    unsigned x;
    asm("cvt.rna.tf32.f32 %0, %1;" : "=r"(x) : "f"(f));
    return x;
}
__device__ __forceinline__ void mma_tf32(float* c, unsigned a0, unsigned a1,
                                         unsigned a2, unsigned a3,
                                         unsigned b0, unsigned b1) {
    asm volatile(
        "mma.sync.aligned.m16n8k8.row.col.f32.tf32.tf32.f32 "
        "{%0,%1,%2,%3}, {%4,%5,%6,%7}, {%8,%9}, {%0,%1,%2,%3};"
        : "+f"(c[0]), "+f"(c[1]), "+f"(c[2]), "+f"(c[3])
        : "r"(a0), "r"(a1), "r"(a2), "r"(a3), "r"(b0), "r"(b1));
}

#define ACT_STRIDE 5           // float4 per row in act buffer (gemm kernels)
#define ACT_BUF    (256 * ACT_STRIDE)

// ---------------- kernel 0: zero agg ----------------
__global__ void zero_agg_kernel() {
    const size_t total4 = (size_t)MCLUS * 132 / 4;
    float4* p = (float4*)g_agg;
    float4 z = make_float4(0.f, 0.f, 0.f, 0.f);
    for (size_t i = blockIdx.x * blockDim.x + threadIdx.x; i < total4;
         i += (size_t)gridDim.x * blockDim.x)
        p[i] = z;
}

// ============ kernel 1: attention MLP (tf32 tensor core) + scatter ============
// 128 points/block, 8 warps. A tile 128x136 fp32 (feat 0..127, rel 128..130, 0 pad).
// Weights 136x64 tf32-rounded (rows 131..135 zero), stride 72 for conflict-free B frags.
#define SA 136
#define SB 72
__global__ void __launch_bounds__(256, 2) att_scatter_kernel(
    const float* __restrict__ feat, const float* __restrict__ pts,
    const float* __restrict__ ctr, const int* __restrict__ lab,
    const float* __restrict__ aW1, const float* __restrict__ ab1,
    const float* __restrict__ aW2, const float* __restrict__ ab2)
{
    extern __shared__ char dynRaw[];
    float*    sA  = (float*)dynRaw;                       // 128*SA floats
    unsigned* sWb = (unsigned*)(dynRaw + 128 * SA * 4);   // 136*SB tf32 bits
    float*    sB1 = (float*)(dynRaw + 128 * SA * 4 + 136 * SB * 4);  // 64
    float*    sA2 = sB1 + 64;          // 64
    float*    sAtt = sA2 + 64;         // 128
    int*      sLab = (int*)(sAtt + 128);  // 128
    float*    sb2p = (float*)(sLab + 128);

    const int tid = threadIdx.x;
    const int gbase = blockIdx.x * 128;
    const float4* f4 = (const float4*)feat;

    // stage A tile: feat cols 0..127 via cp.async (coalesced)
    for (int idx = tid; idx < 128 * 32; idx += 256) {
        int row = idx >> 5, c4 = idx & 31;
        int gr = gbase + row; if (gr >= NPTS) gr = NPTS - 1;
        cpasync16(sA + row * SA + c4 * 4, f4 + (size_t)gr * 32 + c4);
    }
    cp_commit();

    // stage weights (tf32-rounded bits), biases, labels, rel coords
    for (int idx = tid; idx < 136 * 64; idx += 256) {
        int k = idx >> 6, n = idx & 63;
        float v = (k < 131) ? aW1[k * 64 + n] : 0.f;
        sWb[k * SB + n] = cvt_tf32(v);
    }
    if (tid < 64) { sB1[tid] = ab1[tid]; sA2[tid] = aW2[tid]; }
    if (tid == 0) *sb2p = ab2[0];
    if (tid < 128) {
        int row = gbase + tid;
        int rc = (row < NPTS) ? row : (NPTS - 1);
        int l = lab[rc];
        sLab[tid] = l;
        float* Ar = sA + tid * SA;
        Ar[128] = ctr[l * 3 + 0] - pts[rc * 3 + 0];
        Ar[129] = ctr[l * 3 + 1] - pts[rc * 3 + 1];
        Ar[130] = ctr[l * 3 + 2] - pts[rc * 3 + 2];
        Ar[131] = 0.f; Ar[132] = 0.f; Ar[133] = 0.f; Ar[134] = 0.f; Ar[135] = 0.f;
    }
    cp_wait0();
    __syncthreads();

    // ---- tf32 MMA: each warp computes rows w*16..w*16+15 x 64 cols ----
    const int w = tid >> 5;
    const int lane = tid & 31;
    const int g = lane >> 2;
    const int t = lane & 3;

    float acc[8][4];
#pragma unroll
    for (int nf = 0; nf < 8; nf++) {
        acc[nf][0] = 0.f; acc[nf][1] = 0.f; acc[nf][2] = 0.f; acc[nf][3] = 0.f;
    }

    const float* Ar0 = sA + (w * 16 + g) * SA;
    const float* Ar1 = sA + (w * 16 + g + 8) * SA;

#pragma unroll 1
    for (int kf = 0; kf < 17; kf++) {
        int k0 = kf * 8;
        unsigned a0 = cvt_tf32(Ar0[k0 + t]);
        unsigned a1 = cvt_tf32(Ar1[k0 + t]);
        unsigned a2 = cvt_tf32(Ar0[k0 + t + 4]);
        unsigned a3 = cvt_tf32(Ar1[k0 + t + 4]);
        const unsigned* B0 = sWb + (k0 + t) * SB + g;
        const unsigned* B1 = sWb + (k0 + t + 4) * SB + g;
#pragma unroll
        for (int nf = 0; nf < 8; nf++) {
            unsigned b0 = B0[nf * 8];
            unsigned b1 = B1[nf * 8];
            mma_tf32(acc[nf], a0, a1, a2, a3, b0, b1);
        }
    }

    // ---- epilogue: relu -> dot aW2 -> reduce over t lanes -> sigmoid ----
    {
        float s0 = 0.f, s1 = 0.f;
#pragma unroll
        for (int nf = 0; nf < 8; nf++) {
            int c0 = nf * 8 + 2 * t, c1 = c0 + 1;
            float bb0 = sB1[c0], bb1 = sB1[c1];
            float w0 = sA2[c0], w1 = sA2[c1];
            s0 += fmaxf(acc[nf][0] + bb0, 0.f) * w0 + fmaxf(acc[nf][1] + bb1, 0.f) * w1;
            s1 += fmaxf(acc[nf][2] + bb0, 0.f) * w0 + fmaxf(acc[nf][3] + bb1, 0.f) * w1;
        }
        s0 += __shfl_xor_sync(0xffffffffu, s0, 1);
        s0 += __shfl_xor_sync(0xffffffffu, s0, 2);
        s1 += __shfl_xor_sync(0xffffffffu, s1, 1);
        s1 += __shfl_xor_sync(0xffffffffu, s1, 2);
        float b2v = *sb2p;
        if (t == 0) {
            sAtt[w * 16 + g]     = 1.f / (1.f + expf(-(s0 + b2v)));
            sAtt[w * 16 + g + 8] = 1.f / (1.f + expf(-(s1 + b2v)));
        }
    }
    __syncthreads();

    // ---- scatter: 2 threads per row, red4 from the raw-fp32 A tile ----
    {
        int row = tid >> 1, half = tid & 1;
        int grow = gbase + row;
        if (grow < NPTS) {
            float a = sAtt[row];
            int l = sLab[row];
            float* arow = g_agg + (size_t)l * 132;
            const float* Ar = sA + row * SA;
            int c_lo = half ? 17 : 0;
            int c_hi = half ? 33 : 17;   // 33 chunks total: cols 0..131 (131 = 0 pad)
#pragma unroll 1
            for (int c = c_lo; c < c_hi; c++) {
                float4 v = *(const float4*)(Ar + c * 4);
                red4(arow + c * 4, v.x * a, v.y * a, v.z * a, v.w * a);
            }
        }
    }
}

// ============ kernel 2: h = relu(agg @ oW1 + ob1) ============
// grid (196, 2): y = 64-col slice. 4 rows x 16 cols per thread.
__global__ void __launch_bounds__(256, 2) gemmB_kernel(
    const float* __restrict__ oW1, const float* __restrict__ ob1)
{
    extern __shared__ char dynRaw[];
    ulonglong2* sW  = (ulonglong2*)dynRaw;                 // 131*16
    float4*    sAct = (float4*)(dynRaw + 131 * 16 * 16);   // 2 * ACT_BUF

    const int tid = threadIdx.x;
    const int slice = blockIdx.y;
    const int gbase = blockIdx.x * 256;
    const float4* a4 = (const float4*)g_agg;   // 33 f4 per row

    {
        const ulonglong2* wsrc = (const ulonglong2*)oW1;   // 131 x 32
        for (int idx = tid; idx < 131 * 16; idx += 256) {
            int k = idx >> 4, c = idx & 15;
            sW[k * 16 + (c & 3) * 4 + (c >> 2)] = wsrc[k * 32 + slice * 16 + c];
        }
    }
    {
        for (int idx = tid; idx < 256 * 4; idx += 256) {
            int row = idx >> 2, c4 = idx & 3;
            int gr = gbase + row; if (gr >= MCLUS) gr = MCLUS - 1;
            cpasync16(&sAct[row * ACT_STRIDE + c4], a4 + (size_t)gr * 33 + c4);
        }
        cp_commit();
    }
    __syncthreads();

    const int cg = tid & 3;
    const int rg = tid >> 2;

    u64 acc[32];
    {
        const u64* b2 = (const u64*)ob1;
#pragma unroll
        for (int j = 0; j < 8; j++) {
            u64 bb = __ldg(b2 + slice * 32 + cg * 8 + j);
#pragma unroll
            for (int r = 0; r < 4; r++) acc[r * 8 + j] = bb;
        }
    }

#pragma unroll 1
    for (int c = 0; c < 8; c++) {
        cp_wait0();
        __syncthreads();
        if (c < 7) {
            float4* dst = sAct + ((c + 1) & 1) * ACT_BUF;
            for (int idx = tid; idx < 256 * 4; idx += 256) {
                int row = idx >> 2, c4 = idx & 3;
                int gr = gbase + row; if (gr >= MCLUS) gr = MCLUS - 1;
                cpasync16(&dst[row * ACT_STRIDE + c4], a4 + (size_t)gr * 33 + (c + 1) * 4 + c4);
            }
            cp_commit();
        }
        const float4* A = sAct + (c & 1) * ACT_BUF;
#pragma unroll
        for (int k4 = 0; k4 < 4; k4++) {
            float4 av[4];
#pragma unroll
            for (int r = 0; r < 4; r++) av[r] = A[(rg + r * 64) * ACT_STRIDE + k4];
#pragma unroll
            for (int e = 0; e < 4; e++) {
                const ulonglong2* wp = sW + (c * 16 + k4 * 4 + e) * 16 + cg;
                ulonglong2 wa = wp[0], wb = wp[4], wc = wp[8], wd = wp[12];
                u64 wv[8] = {wa.x, wa.y, wb.x, wb.y, wc.x, wc.y, wd.x, wd.y};
#pragma unroll
                for (int r = 0; r < 4; r++) {
                    float ae = elem4(av[r], e);
                    u64 tp = pack2(ae, ae);
#pragma unroll
                    for (int j = 0; j < 8; j++)
                        acc[r * 8 + j] = fma2(tp, wv[j], acc[r * 8 + j]);
                }
            }
        }
    }

    // tail k = 128..130
    {
        float4 tv[4];
#pragma unroll
        for (int r = 0; r < 4; r++) {
            int gr = gbase + rg + r * 64; if (gr >= MCLUS) gr = MCLUS - 1;
            tv[r] = a4[(size_t)gr * 33 + 32];
        }
#pragma unroll
        for (int e = 0; e < 3; e++) {
            const ulonglong2* wp = sW + (128 + e) * 16 + cg;
            ulonglong2 wa = wp[0], wb = wp[4], wc = wp[8], wd = wp[12];
            u64 wv[8] = {wa.x, wa.y, wb.x, wb.y, wc.x, wc.y, wd.x, wd.y};
#pragma unroll
            for (int r = 0; r < 4; r++) {
                float ae = elem4(tv[r], e);
                u64 tp = pack2(ae, ae);
#pragma unroll
                for (int j = 0; j < 8; j++)
                    acc[r * 8 + j] = fma2(tp, wv[j], acc[r * 8 + j]);
            }
        }
    }

#pragma unroll
    for (int r = 0; r < 4; r++) {
        int rr = gbase + rg + r * 64;
        if (rr < MCLUS) {
            float2* hp = (float2*)(g_h + (size_t)rr * 128 + slice * 64 + cg * 16);
#pragma unroll
            for (int j = 0; j < 8; j++) {
                float2 v = unpack2(acc[r * 8 + j]);
                v.x = fmaxf(v.x, 0.f);
                v.y = fmaxf(v.y, 0.f);
                hp[j] = v;
            }
        }
    }
}

// ============ kernel 3: out = relu(h @ oW2 + ob2) ============
// grid (196, 4): y = 64-col slice.
__global__ void __launch_bounds__(256, 2) gemmC_kernel(
    const float* __restrict__ oW2, const float* __restrict__ ob2,
    float* __restrict__ out)
{
    extern __shared__ char dynRaw[];
    ulonglong2* sW  = (ulonglong2*)dynRaw;                 // 128*16
    float4*    sAct = (float4*)(dynRaw + 128 * 16 * 16);   // 2 * ACT_BUF

    const int tid = threadIdx.x;
    const int slice = blockIdx.y;
    const int gbase = blockIdx.x * 256;
    const float4* h4 = (const float4*)g_h;   // 32 f4 per row

    {
        const ulonglong2* wsrc = (const ulonglong2*)oW2;   // 128 x 64
        for (int idx = tid; idx < 128 * 16; idx += 256) {
            int k = idx >> 4, c = idx & 15;
            sW[k * 16 + (c & 3) * 4 + (c >> 2)] = wsrc[k * 64 + slice * 16 + c];
        }
    }
    {
        for (int idx = tid; idx < 256 * 4; idx += 256) {
            int row = idx >> 2, c4 = idx & 3;
            int gr = gbase + row; if (gr >= MCLUS) gr = MCLUS - 1;
            cpasync16(&sAct[row * ACT_STRIDE + c4], h4 + (size_t)gr * 32 + c4);
        }
        cp_commit();
    }
    __syncthreads();

    const int cg = tid & 3;
    const int rg = tid >> 2;

    u64 acc[32];
    {
        const u64* b2 = (const u64*)ob2;
#pragma unroll
        for (int j = 0; j < 8; j++) {
            u64 bb = __ldg(b2 + slice * 32 + cg * 8 + j);
#pragma unroll
            for (int r = 0; r < 4; r++) acc[r * 8 + j] = bb;
        }
    }

#pragma unroll 1
    for (int c = 0; c < 8; c++) {
        cp_wait0();
        __syncthreads();
        if (c < 7) {
            float4* dst = sAct + ((c + 1) & 1) * ACT_BUF;
            for (int idx = tid; idx < 256 * 4; idx += 256) {
                int row = idx >> 2, c4 = idx & 3;
                int gr = gbase + row; if (gr >= MCLUS) gr = MCLUS - 1;
                cpasync16(&dst[row * ACT_STRIDE + c4], h4 + (size_t)gr * 32 + (c + 1) * 4 + c4);
            }
            cp_commit();
        }
        const float4* A = sAct + (c & 1) * ACT_BUF;
#pragma unroll
        for (int k4 = 0; k4 < 4; k4++) {
            float4 av[4];
#pragma unroll
            for (int r = 0; r < 4; r++) av[r] = A[(rg + r * 64) * ACT_STRIDE + k4];
#pragma unroll
            for (int e = 0; e < 4; e++) {
                const ulonglong2* wp = sW + (c * 16 + k4 * 4 + e) * 16 + cg;
                ulonglong2 wa = wp[0], wb = wp[4], wc = wp[8], wd = wp[12];
                u64 wv[8] = {wa.x, wa.y, wb.x, wb.y, wc.x, wc.y, wd.x, wd.y};
#pragma unroll
                for (int r = 0; r < 4; r++) {
                    float ae = elem4(av[r], e);
                    u64 tp = pack2(ae, ae);
#pragma unroll
                    for (int j = 0; j < 8; j++)
                        acc[r * 8 + j] = fma2(tp, wv[j], acc[r * 8 + j]);
                }
            }
        }
    }

#pragma unroll
    for (int r = 0; r < 4; r++) {
        int rr = gbase + rg + r * 64;
        if (rr < MCLUS) {
            float2* op = (float2*)(out + (size_t)rr * 256 + slice * 64 + cg * 16);
#pragma unroll
            for (int j = 0; j < 8; j++) {
                float2 v = unpack2(acc[r * 8 + j]);
                v.x = fmaxf(v.x, 0.f);
                v.y = fmaxf(v.y, 0.f);
                op[j] = v;
            }
        }
    }
}

extern "C" void kernel_launch(void* const* d_in, const int* in_sizes, int n_in,
                              void* d_out, int out_size) {
    const float* feat = (const float*)d_in[0];
    const float* pts  = (const float*)d_in[1];
    const float* ctr  = (const float*)d_in[2];
    const int*   lab  = (const int*)d_in[3];
    const float* aW1  = (const float*)d_in[4];
    const float* ab1  = (const float*)d_in[5];
    const float* aW2  = (const float*)d_in[6];
    const float* ab2  = (const float*)d_in[7];
    const float* oW1  = (const float*)d_in[8];
    const float* ob1  = (const float*)d_in[9];
    const float* oW2  = (const float*)d_in[10];
    const float* ob2  = (const float*)d_in[11];
    float* out = (float*)d_out;

    const int attSmem = 128 * SA * 4 + 136 * SB * 4 + (64 + 64 + 128) * 4 + 128 * 4 + 16;
    const int bSmem   = 131 * 16 * 16 + 2 * ACT_BUF * 16;
    const int cSmem   = 128 * 16 * 16 + 2 * ACT_BUF * 16;

    static int inited = 0;
    if (!inited) {
        cudaFuncSetAttribute(att_scatter_kernel, cudaFuncAttributeMaxDynamicSharedMemorySize, attSmem);
        cudaFuncSetAttribute(gemmB_kernel, cudaFuncAttributeMaxDynamicSharedMemorySize, bSmem);
        cudaFuncSetAttribute(gemmC_kernel, cudaFuncAttributeMaxDynamicSharedMemorySize, cSmem);
        inited = 1;
    }

    zero_agg_kernel<<<2048, 256>>>();
    att_scatter_kernel<<<(NPTS + 127) / 128, 256, attSmem>>>(feat, pts, ctr, lab,
                                                             aW1, ab1, aW2, ab2);
    gemmB_kernel<<<dim3((MCLUS + 255) / 256, 2), 256, bSmem>>>(oW1, ob1);
    gemmC_kernel<<<dim3((MCLUS + 255) / 256, 4), 256, cSmem>>>(oW2, ob2, out);
}

// round 8
// speedup vs baseline: 1.9715x; 1.2593x over previous
#include <cuda_runtime.h>
#include <math.h>

#define NPTS   500000
#define MCLUS  50000

typedef unsigned long long u64;

__device__ float g_agg[(size_t)MCLUS * 132];   // 131 used + 1 pad
__device__ float g_h[(size_t)MCLUS * 128];

// ---------------- helpers ----------------
__device__ __forceinline__ void red4(float* addr, float a, float b, float c, float d) {
    asm volatile("red.global.add.v4.f32 [%0], {%1,%2,%3,%4};"
                 :: "l"(addr), "f"(a), "f"(b), "f"(c), "f"(d) : "memory");
}
__device__ __forceinline__ void cpasync16(void* smem_dst, const void* gsrc) {
    unsigned saddr = (unsigned)__cvta_generic_to_shared(smem_dst);
    asm volatile("cp.async.ca.shared.global [%0], [%1], 16;" :: "r"(saddr), "l"(gsrc));
}
__device__ __forceinline__ void cp_commit() { asm volatile("cp.async.commit_group;"); }
__device__ __forceinline__ void cp_wait0()  { asm volatile("cp.async.wait_group 0;" ::: "memory"); }

__device__ __forceinline__ unsigned cvt_tf32(float f) {
    unsigned x;
    asm("cvt.rna.tf32.f32 %0, %1;" : "=r"(x) : "f"(f));
    return x;
}
__device__ __forceinline__ void mma_tf32(float* c, unsigned a0, unsigned a1,
                                         unsigned a2, unsigned a3,
                                         unsigned b0, unsigned b1) {
    asm volatile(
        "mma.sync.aligned.m16n8k8.row.col.f32.tf32.tf32.f32 "
        "{%0,%1,%2,%3}, {%4,%5,%6,%7}, {%8,%9}, {%0,%1,%2,%3};"
        : "+f"(c[0]), "+f"(c[1]), "+f"(c[2]), "+f"(c[3])
        : "r"(a0), "r"(a1), "r"(a2), "r"(a3), "r"(b0), "r"(b1));
}

#define SA 136   // A-tile row stride (floats): bank = (8g+t)%32 -> conflict-free
#define SB 72    // B-tile row stride (tf32 words): conflict-free

// ---------------- kernel 0: zero agg ----------------
__global__ void zero_agg_kernel() {
    const size_t total4 = (size_t)MCLUS * 132 / 4;
    float4* p = (float4*)g_agg;
    float4 z = make_float4(0.f, 0.f, 0.f, 0.f);
    for (size_t i = blockIdx.x * blockDim.x + threadIdx.x; i < total4;
         i += (size_t)gridDim.x * blockDim.x)
        p[i] = z;
}

// ============ kernel 1: attention MLP (tf32 MMA) + scatter ============
__global__ void __launch_bounds__(256, 2) att_scatter_kernel(
    const float* __restrict__ feat, const float* __restrict__ pts,
    const float* __restrict__ ctr, const int* __restrict__ lab,
    const float* __restrict__ aW1, const float* __restrict__ ab1,
    const float* __restrict__ aW2, const float* __restrict__ ab2)
{
    extern __shared__ char dynRaw[];
    float*    sA  = (float*)dynRaw;                       // 128*SA floats
    unsigned* sWb = (unsigned*)(dynRaw + 128 * SA * 4);   // 136*SB tf32 bits
    float*    sB1 = (float*)(dynRaw + 128 * SA * 4 + 136 * SB * 4);  // 64
    float*    sA2 = sB1 + 64;          // 64
    float*    sAtt = sA2 + 64;         // 128
    int*      sLab = (int*)(sAtt + 128);  // 128
    float*    sb2p = (float*)(sLab + 128);

    const int tid = threadIdx.x;
    const int gbase = blockIdx.x * 128;
    const float4* f4 = (const float4*)feat;

    for (int idx = tid; idx < 128 * 32; idx += 256) {
        int row = idx >> 5, c4 = idx & 31;
        int gr = gbase + row; if (gr >= NPTS) gr = NPTS - 1;
        cpasync16(sA + row * SA + c4 * 4, f4 + (size_t)gr * 32 + c4);
    }
    cp_commit();

    for (int idx = tid; idx < 136 * 64; idx += 256) {
        int k = idx >> 6, n = idx & 63;
        float v = (k < 131) ? aW1[k * 64 + n] : 0.f;
        sWb[k * SB + n] = cvt_tf32(v);
    }
    if (tid < 64) { sB1[tid] = ab1[tid]; sA2[tid] = aW2[tid]; }
    if (tid == 0) *sb2p = ab2[0];
    if (tid < 128) {
        int row = gbase + tid;
        int rc = (row < NPTS) ? row : (NPTS - 1);
        int l = lab[rc];
        sLab[tid] = l;
        float* Ar = sA + tid * SA;
        Ar[128] = ctr[l * 3 + 0] - pts[rc * 3 + 0];
        Ar[129] = ctr[l * 3 + 1] - pts[rc * 3 + 1];
        Ar[130] = ctr[l * 3 + 2] - pts[rc * 3 + 2];
        Ar[131] = 0.f; Ar[132] = 0.f; Ar[133] = 0.f; Ar[134] = 0.f; Ar[135] = 0.f;
    }
    cp_wait0();
    __syncthreads();

    const int w = tid >> 5;
    const int lane = tid & 31;
    const int g = lane >> 2;
    const int t = lane & 3;

    float acc[8][4];
#pragma unroll
    for (int nf = 0; nf < 8; nf++) {
        acc[nf][0] = 0.f; acc[nf][1] = 0.f; acc[nf][2] = 0.f; acc[nf][3] = 0.f;
    }

    const float* Ar0 = sA + (w * 16 + g) * SA;
    const float* Ar1 = sA + (w * 16 + g + 8) * SA;

#pragma unroll 1
    for (int kf = 0; kf < 17; kf++) {
        int k0 = kf * 8;
        unsigned a0 = cvt_tf32(Ar0[k0 + t]);
        unsigned a1 = cvt_tf32(Ar1[k0 + t]);
        unsigned a2 = cvt_tf32(Ar0[k0 + t + 4]);
        unsigned a3 = cvt_tf32(Ar1[k0 + t + 4]);
        const unsigned* B0 = sWb + (k0 + t) * SB + g;
        const unsigned* B1 = sWb + (k0 + t + 4) * SB + g;
#pragma unroll
        for (int nf = 0; nf < 8; nf++) {
            mma_tf32(acc[nf], a0, a1, a2, a3, B0[nf * 8], B1[nf * 8]);
        }
    }

    {
        float s0 = 0.f, s1 = 0.f;
#pragma unroll
        for (int nf = 0; nf < 8; nf++) {
            int c0 = nf * 8 + 2 * t, c1 = c0 + 1;
            float bb0 = sB1[c0], bb1 = sB1[c1];
            float w0 = sA2[c0], w1 = sA2[c1];
            s0 += fmaxf(acc[nf][0] + bb0, 0.f) * w0 + fmaxf(acc[nf][1] + bb1, 0.f) * w1;
            s1 += fmaxf(acc[nf][2] + bb0, 0.f) * w0 + fmaxf(acc[nf][3] + bb1, 0.f) * w1;
        }
        s0 += __shfl_xor_sync(0xffffffffu, s0, 1);
        s0 += __shfl_xor_sync(0xffffffffu, s0, 2);
        s1 += __shfl_xor_sync(0xffffffffu, s1, 1);
        s1 += __shfl_xor_sync(0xffffffffu, s1, 2);
        float b2v = *sb2p;
        if (t == 0) {
            sAtt[w * 16 + g]     = 1.f / (1.f + expf(-(s0 + b2v)));
            sAtt[w * 16 + g + 8] = 1.f / (1.f + expf(-(s1 + b2v)));
        }
    }
    __syncthreads();

    {
        int row = tid >> 1, half = tid & 1;
        int grow = gbase + row;
        if (grow < NPTS) {
            float a = sAtt[row];
            int l = sLab[row];
            float* arow = g_agg + (size_t)l * 132;
            const float* Ar = sA + row * SA;
            int c_lo = half ? 17 : 0;
            int c_hi = half ? 33 : 17;
#pragma unroll 1
            for (int c = c_lo; c < c_hi; c++) {
                float4 v = *(const float4*)(Ar + c * 4);
                red4(arow + c * 4, v.x * a, v.y * a, v.z * a, v.w * a);
            }
        }
    }
}

// ============ kernel 2: h = relu(agg @ oW1 + ob1)  (tf32 MMA) ============
// grid (391, 2): y = 64-col slice; 128 rows/block; K = 132 (136 padded)
__global__ void __launch_bounds__(256, 2) gemmB_kernel(
    const float* __restrict__ oW1, const float* __restrict__ ob1)
{
    extern __shared__ char dynRaw[];
    float*    sA  = (float*)dynRaw;                       // 128*SA
    unsigned* sWb = (unsigned*)(dynRaw + 128 * SA * 4);   // 136*SB

    const int tid = threadIdx.x;
    const int slice = blockIdx.y;
    const int gbase = blockIdx.x * 128;
    const float4* a4 = (const float4*)g_agg;   // 33 f4/row

    for (int idx = tid; idx < 128 * 33; idx += 256) {
        int row = idx / 33, c4 = idx - row * 33;
        int gr = gbase + row; if (gr >= MCLUS) gr = MCLUS - 1;
        cpasync16(sA + row * SA + c4 * 4, a4 + (size_t)gr * 33 + c4);
    }
    cp_commit();

    for (int idx = tid; idx < 136 * 64; idx += 256) {
        int k = idx >> 6, n = idx & 63;
        float v = (k < 131) ? oW1[k * 128 + slice * 64 + n] : 0.f;
        sWb[k * SB + n] = cvt_tf32(v);
    }
    if (tid < 128) {   // zero A cols 132..135 (avoid NaN * 0)
        float* Ar = sA + tid * SA;
        Ar[132] = 0.f; Ar[133] = 0.f; Ar[134] = 0.f; Ar[135] = 0.f;
    }
    cp_wait0();
    __syncthreads();

    const int w = tid >> 5;
    const int lane = tid & 31;
    const int g = lane >> 2;
    const int t = lane & 3;

    float acc[8][4];
#pragma unroll
    for (int nf = 0; nf < 8; nf++) {
        acc[nf][0] = 0.f; acc[nf][1] = 0.f; acc[nf][2] = 0.f; acc[nf][3] = 0.f;
    }

    const float* Ar0 = sA + (w * 16 + g) * SA;
    const float* Ar1 = sA + (w * 16 + g + 8) * SA;

#pragma unroll 1
    for (int kf = 0; kf < 17; kf++) {
        int k0 = kf * 8;
        unsigned a0 = cvt_tf32(Ar0[k0 + t]);
        unsigned a1 = cvt_tf32(Ar1[k0 + t]);
        unsigned a2 = cvt_tf32(Ar0[k0 + t + 4]);
        unsigned a3 = cvt_tf32(Ar1[k0 + t + 4]);
        const unsigned* B0 = sWb + (k0 + t) * SB + g;
        const unsigned* B1 = sWb + (k0 + t + 4) * SB + g;
#pragma unroll
        for (int nf = 0; nf < 8; nf++) {
            mma_tf32(acc[nf], a0, a1, a2, a3, B0[nf * 8], B1[nf * 8]);
        }
    }

    // epilogue: bias + relu -> g_h
    int r0 = gbase + w * 16 + g;
    int r1 = r0 + 8;
#pragma unroll
    for (int nf = 0; nf < 8; nf++) {
        int c0 = slice * 64 + nf * 8 + 2 * t;
        float bb0 = __ldg(ob1 + c0), bb1 = __ldg(ob1 + c0 + 1);
        if (r0 < MCLUS) {
            float2 v = make_float2(fmaxf(acc[nf][0] + bb0, 0.f),
                                   fmaxf(acc[nf][1] + bb1, 0.f));
            *(float2*)(g_h + (size_t)r0 * 128 + c0) = v;
        }
        if (r1 < MCLUS) {
            float2 v = make_float2(fmaxf(acc[nf][2] + bb0, 0.f),
                                   fmaxf(acc[nf][3] + bb1, 0.f));
            *(float2*)(g_h + (size_t)r1 * 128 + c0) = v;
        }
    }
}

// ============ kernel 3: out = relu(h @ oW2 + ob2)  (tf32 MMA) ============
// grid (391, 4): y = 64-col slice; 128 rows/block; K = 128
__global__ void __launch_bounds__(256, 2) gemmC_kernel(
    const float* __restrict__ oW2, const float* __restrict__ ob2,
    float* __restrict__ out)
{
    extern __shared__ char dynRaw[];
    float*    sA  = (float*)dynRaw;                       // 128*SA
    unsigned* sWb = (unsigned*)(dynRaw + 128 * SA * 4);   // 128*SB

    const int tid = threadIdx.x;
    const int slice = blockIdx.y;
    const int gbase = blockIdx.x * 128;
    const float4* h4 = (const float4*)g_h;   // 32 f4/row

    for (int idx = tid; idx < 128 * 32; idx += 256) {
        int row = idx >> 5, c4 = idx & 31;
        int gr = gbase + row; if (gr >= MCLUS) gr = MCLUS - 1;
        cpasync16(sA + row * SA + c4 * 4, h4 + (size_t)gr * 32 + c4);
    }
    cp_commit();

    for (int idx = tid; idx < 128 * 64; idx += 256) {
        int k = idx >> 6, n = idx & 63;
        sWb[k * SB + n] = cvt_tf32(oW2[k * 256 + slice * 64 + n]);
    }
    cp_wait0();
    __syncthreads();

    const int w = tid >> 5;
    const int lane = tid & 31;
    const int g = lane >> 2;
    const int t = lane & 3;

    float acc[8][4];
#pragma unroll
    for (int nf = 0; nf < 8; nf++) {
        acc[nf][0] = 0.f; acc[nf][1] = 0.f; acc[nf][2] = 0.f; acc[nf][3] = 0.f;
    }

    const float* Ar0 = sA + (w * 16 + g) * SA;
    const float* Ar1 = sA + (w * 16 + g + 8) * SA;

#pragma unroll 1
    for (int kf = 0; kf < 16; kf++) {
        int k0 = kf * 8;
        unsigned a0 = cvt_tf32(Ar0[k0 + t]);
        unsigned a1 = cvt_tf32(Ar1[k0 + t]);
        unsigned a2 = cvt_tf32(Ar0[k0 + t + 4]);
        unsigned a3 = cvt_tf32(Ar1[k0 + t + 4]);
        const unsigned* B0 = sWb + (k0 + t) * SB + g;
        const unsigned* B1 = sWb + (k0 + t + 4) * SB + g;
#pragma unroll
        for (int nf = 0; nf < 8; nf++) {
            mma_tf32(acc[nf], a0, a1, a2, a3, B0[nf * 8], B1[nf * 8]);
        }
    }

    int r0 = gbase + w * 16 + g;
    int r1 = r0 + 8;
#pragma unroll
    for (int nf = 0; nf < 8; nf++) {
        int c0 = slice * 64 + nf * 8 + 2 * t;
        float bb0 = __ldg(ob2 + c0), bb1 = __ldg(ob2 + c0 + 1);
        if (r0 < MCLUS) {
            float2 v = make_float2(fmaxf(acc[nf][0] + bb0, 0.f),
                                   fmaxf(acc[nf][1] + bb1, 0.f));
            *(float2*)(out + (size_t)r0 * 256 + c0) = v;
        }
        if (r1 < MCLUS) {
            float2 v = make_float2(fmaxf(acc[nf][2] + bb0, 0.f),
                                   fmaxf(acc[nf][3] + bb1, 0.f));
            *(float2*)(out + (size_t)r1 * 256 + c0) = v;
        }
    }
}

extern "C" void kernel_launch(void* const* d_in, const int* in_sizes, int n_in,
                              void* d_out, int out_size) {
    const float* feat = (const float*)d_in[0];
    const float* pts  = (const float*)d_in[1];
    const float* ctr  = (const float*)d_in[2];
    const int*   lab  = (const int*)d_in[3];
    const float* aW1  = (const float*)d_in[4];
    const float* ab1  = (const float*)d_in[5];
    const float* aW2  = (const float*)d_in[6];
    const float* ab2  = (const float*)d_in[7];
    const float* oW1  = (const float*)d_in[8];
    const float* ob1  = (const float*)d_in[9];
    const float* oW2  = (const float*)d_in[10];
    const float* ob2  = (const float*)d_in[11];
    float* out = (float*)d_out;

    const int attSmem = 128 * SA * 4 + 136 * SB * 4 + (64 + 64 + 128) * 4 + 128 * 4 + 16;
    const int bSmem   = 128 * SA * 4 + 136 * SB * 4;
    const int cSmem   = 128 * SA * 4 + 128 * SB * 4;

    static int inited = 0;
    if (!inited) {
        cudaFuncSetAttribute(att_scatter_kernel, cudaFuncAttributeMaxDynamicSharedMemorySize, attSmem);
        cudaFuncSetAttribute(gemmB_kernel, cudaFuncAttributeMaxDynamicSharedMemorySize, bSmem);
        cudaFuncSetAttribute(gemmC_kernel, cudaFuncAttributeMaxDynamicSharedMemorySize, cSmem);
        inited = 1;
    }

    zero_agg_kernel<<<2048, 256>>>();
    att_scatter_kernel<<<(NPTS + 127) / 128, 256, attSmem>>>(feat, pts, ctr, lab,
                                                             aW1, ab1, aW2, ab2);
    gemmB_kernel<<<dim3((MCLUS + 127) / 128, 2), 256, bSmem>>>(oW1, ob1);
    gemmC_kernel<<<dim3((MCLUS + 127) / 128, 4), 256, cSmem>>>(oW2, ob2, out);
}